// round 6
// baseline (speedup 1.0000x reference)
#include <cuda_runtime.h>
#include <cuda_bf16.h>
#include <cstdint>

#define B_ 2
#define S_ 2048
#define D_ 1024
#define H_ 16
#define DK_ 64
#define OUT_ELEMS (B_*S_*D_)           /* 4194304  */
#define ATT_ELEMS (B_*H_*S_*S_)        /* 134217728 */

// ---------------- scratch (device globals; no allocation allowed) ----------
__device__ __nv_bfloat16 g_Qhi[B_*H_*S_*DK_];  // head-major, pre-scaled by 1/8
__device__ __nv_bfloat16 g_Qlo[B_*H_*S_*DK_];
__device__ __nv_bfloat16 g_Khi[B_*H_*S_*DK_];
__device__ __nv_bfloat16 g_Klo[B_*H_*S_*DK_];
__device__ __nv_bfloat16 g_Vhi[B_*H_*S_*DK_];
__device__ __nv_bfloat16 g_Vlo[B_*H_*S_*DK_];
__device__ float g_C[B_*S_*D_];        // context, token-major
__device__ float g_L[B_*H_*S_];        // softmax row sums

__device__ __forceinline__ uint32_t smem_u32(const void* p) {
    uint32_t a;
    asm("{ .reg .u64 t; cvta.to.shared.u64 t, %1; cvt.u32.u64 %0, t; }" : "=r"(a) : "l"(p));
    return a;
}

// ---------------- mma.sync / async-copy primitives (baseline PTX) ----------
__device__ __forceinline__ void ldsm_x4(uint32_t (&r)[4], uint32_t addr) {
    asm volatile("ldmatrix.sync.aligned.m8n8.x4.shared.b16 {%0,%1,%2,%3}, [%4];"
        : "=r"(r[0]), "=r"(r[1]), "=r"(r[2]), "=r"(r[3]) : "r"(addr));
}
__device__ __forceinline__ void ldsm_x2(uint32_t (&r)[2], uint32_t addr) {
    asm volatile("ldmatrix.sync.aligned.m8n8.x2.shared.b16 {%0,%1}, [%2];"
        : "=r"(r[0]), "=r"(r[1]) : "r"(addr));
}
__device__ __forceinline__ void ldsm_x2t(uint32_t (&r)[2], uint32_t addr) {
    asm volatile("ldmatrix.sync.aligned.m8n8.x2.trans.shared.b16 {%0,%1}, [%2];"
        : "=r"(r[0]), "=r"(r[1]) : "r"(addr));
}
__device__ __forceinline__ void mma16816(float (&c)[4], const uint32_t (&a)[4],
                                         const uint32_t (&b)[2]) {
    asm volatile("mma.sync.aligned.m16n8k16.row.col.f32.bf16.bf16.f32 "
        "{%0,%1,%2,%3}, {%4,%5,%6,%7}, {%8,%9}, {%0,%1,%2,%3};"
        : "+f"(c[0]), "+f"(c[1]), "+f"(c[2]), "+f"(c[3])
        : "r"(a[0]), "r"(a[1]), "r"(a[2]), "r"(a[3]), "r"(b[0]), "r"(b[1]));
}
#define CP16(dst, src) \
    asm volatile("cp.async.cg.shared.global [%0], [%1], 16;" :: "r"(dst), "l"(src))
#define CP_COMMIT() asm volatile("cp.async.commit_group;" ::: "memory")
#define CP_WAIT(n)  asm volatile("cp.async.wait_group %0;" :: "n"(n) : "memory")

__device__ __forceinline__ uint32_t packbf(float lo, float hi) {
    uint32_t r;
    asm("cvt.rn.bf16x2.f32 %0, %1, %2;" : "=r"(r) : "f"(hi), "f"(lo));
    return r;
}
__device__ __forceinline__ float bf_round(float x) {
    return __bfloat162float(__float2bfloat16(x));
}
__device__ __forceinline__ void cvt4(uint2 &hi, uint2 &lo, float4 vv) {
    float v0 = vv.x, v1 = vv.y, v2 = vv.z, v3 = vv.w;
    __nv_bfloat16 h0 = __float2bfloat16(v0), h1 = __float2bfloat16(v1);
    __nv_bfloat16 h2 = __float2bfloat16(v2), h3 = __float2bfloat16(v3);
    __nv_bfloat162 hh0(h0, h1), hh1(h2, h3);
    __nv_bfloat162 ll0(__float2bfloat16(v0 - __bfloat162float(h0)),
                       __float2bfloat16(v1 - __bfloat162float(h1)));
    __nv_bfloat162 ll1(__float2bfloat16(v2 - __bfloat162float(h2)),
                       __float2bfloat16(v3 - __bfloat162float(h3)));
    hi = make_uint2(*(uint32_t*)&hh0, *(uint32_t*)&hh1);
    lo = make_uint2(*(uint32_t*)&ll0, *(uint32_t*)&ll1);
}

// ===========================================================================
// Split-bf16 tensor-core GEMM.  mode 0: epilogue emits split-bf16 (hi,lo)
// head-major Q/K/V scratch.  mode 1: fp32 row-major (final output).
// ===========================================================================
#define PITCH 40
#define MAT_U (128*PITCH)
#define STAGE_U (4*MAT_U)
#define GT_SMEM (2*STAGE_U*2)

__device__ __forceinline__ size_t ymap0(int m, int n) {   // head-major
    return (((size_t)((m >> 11) * 16 + (n >> 6))) * 2048 + (m & 2047)) * 64 + (n & 63);
}

__global__ __launch_bounds__(256) void mma_gemm(
    const float* __restrict__ X, const float* __restrict__ W,
    __nv_bfloat16* __restrict__ Yhi, __nv_bfloat16* __restrict__ Ylo,
    float* __restrict__ Yf, float scale, int mode)
{
    extern __shared__ __nv_bfloat16 sh[];
    const uint32_t sh0 = smem_u32(sh);

    const int t = threadIdx.x;
    const int warp = t >> 5, lane = t & 31;
    const int bm = blockIdx.y * 128, bn = blockIdx.x * 128;
    const int wm = (warp >> 1) * 32;
    const int wn = (warp & 1) * 64;
    const int lr = t >> 3, lc = (t & 7) * 4;

    float4 ra[4], rb[4];
    float acc[2][8][4];
    #pragma unroll
    for (int mt = 0; mt < 2; mt++)
        #pragma unroll
        for (int nt = 0; nt < 8; nt++)
            #pragma unroll
            for (int j = 0; j < 4; j++) acc[mt][nt][j] = 0.f;

    const int r8 = lane & 7, tl = lane >> 3;
    const uint32_t a_row = (uint32_t)(wm + (tl & 1) * 8 + r8);
    const uint32_t a_col = (uint32_t)((tl >> 1) * 16);
    const uint32_t b_row = (uint32_t)(wn + r8);
    const uint32_t b_col = (uint32_t)((tl & 1) * 16);

    #define GEMM_LDG(c) do {                                                     \
        const float* xp = X + (size_t)(bm + lr) * 1024 + (c) * 32 + lc;          \
        const float* wp = W + (size_t)(bn + lr) * 1024 + (c) * 32 + lc;          \
        _Pragma("unroll")                                                        \
        for (int p = 0; p < 4; p++) {                                            \
            ra[p] = *(const float4*)(xp + (size_t)p * 32 * 1024);                \
            rb[p] = *(const float4*)(wp + (size_t)p * 32 * 1024);                \
        }                                                                        \
    } while (0)

    #define GEMM_STS(s) do {                                                     \
        __nv_bfloat16* Ah = sh + (s) * STAGE_U;                                  \
        __nv_bfloat16* Al = Ah + MAT_U;                                          \
        __nv_bfloat16* Bh = Ah + 2 * MAT_U;                                      \
        __nv_bfloat16* Bl = Ah + 3 * MAT_U;                                      \
        _Pragma("unroll")                                                        \
        for (int p = 0; p < 4; p++) {                                            \
            int row = lr + p * 32;                                               \
            uint2 hi, lo;                                                        \
            cvt4(hi, lo, ra[p]);                                                 \
            *(uint2*)&Ah[row * PITCH + lc] = hi;                                 \
            *(uint2*)&Al[row * PITCH + lc] = lo;                                 \
            cvt4(hi, lo, rb[p]);                                                 \
            *(uint2*)&Bh[row * PITCH + lc] = hi;                                 \
            *(uint2*)&Bl[row * PITCH + lc] = lo;                                 \
        }                                                                        \
    } while (0)

    #define GEMM_COMPUTE(s) do {                                                 \
        uint32_t Ahi = sh0 + (s) * STAGE_U * 2;                                  \
        uint32_t Alo = Ahi + MAT_U * 2;                                          \
        uint32_t Bhi = Ahi + 2 * MAT_U * 2;                                      \
        uint32_t Blo = Ahi + 3 * MAT_U * 2;                                      \
        _Pragma("unroll")                                                        \
        for (int ks = 0; ks < 2; ks++) {                                         \
            uint32_t ah[2][4], al[2][4];                                         \
            _Pragma("unroll")                                                    \
            for (int mt = 0; mt < 2; mt++) {                                     \
                uint32_t off = (a_row + mt * 16) * 80 + a_col + ks * 32;         \
                ldsm_x4(ah[mt], Ahi + off);                                      \
                ldsm_x4(al[mt], Alo + off);                                      \
            }                                                                    \
            _Pragma("unroll")                                                    \
            for (int nt = 0; nt < 8; nt++) {                                     \
                uint32_t boff = (b_row + nt * 8) * 80 + b_col + ks * 32;         \
                uint32_t bh[2], bl[2];                                           \
                ldsm_x2(bh, Bhi + boff);                                         \
                ldsm_x2(bl, Blo + boff);                                         \
                _Pragma("unroll")                                                \
                for (int mt = 0; mt < 2; mt++) {                                 \
                    mma16816(acc[mt][nt], ah[mt], bh);                           \
                    mma16816(acc[mt][nt], ah[mt], bl);                           \
                    mma16816(acc[mt][nt], al[mt], bh);                           \
                }                                                                \
            }                                                                    \
        }                                                                        \
    } while (0)

    GEMM_LDG(0);
    GEMM_STS(0);
    __syncthreads();
    for (int c = 0; c < 32; c++) {
        if (c < 31) GEMM_LDG(c + 1);
        GEMM_COMPUTE(c & 1);
        __syncthreads();
        if (c < 31) { GEMM_STS((c + 1) & 1); __syncthreads(); }
    }

    const int er = lane >> 2, ec = (lane & 3) * 2;
    #pragma unroll
    for (int mt = 0; mt < 2; mt++)
        #pragma unroll
        for (int nt = 0; nt < 8; nt++) {
            int m = bm + wm + mt * 16 + er;
            int n = bn + wn + nt * 8 + ec;
            float v00 = acc[mt][nt][0] * scale, v01 = acc[mt][nt][1] * scale;
            float v10 = acc[mt][nt][2] * scale, v11 = acc[mt][nt][3] * scale;
            if (mode == 0) {
                size_t i0 = ymap0(m, n), i1 = ymap0(m + 8, n);
                float h00 = bf_round(v00), h01 = bf_round(v01);
                float h10 = bf_round(v10), h11 = bf_round(v11);
                *(uint32_t*)&Yhi[i0] = packbf(h00, h01);
                *(uint32_t*)&Ylo[i0] = packbf(v00 - h00, v01 - h01);
                *(uint32_t*)&Yhi[i1] = packbf(h10, h11);
                *(uint32_t*)&Ylo[i1] = packbf(v10 - h10, v11 - h11);
            } else {
                *(float2*)&Yf[(size_t)m * 1024 + n]       = make_float2(v00, v01);
                *(float2*)&Yf[(size_t)(m + 8) * 1024 + n] = make_float2(v10, v11);
            }
        }
}

// ===========================================================================
// Tensor-core attention: pre-split bf16 inputs, cp.async double-buffered.
// Per (b,h,128-q tile), 8 warps (4q x 2k), 64-key chunks.
// ===========================================================================
#define APB 144                        /* bytes per 64-bf16 row (128 + 16 pad) */
#define AQHI 0
#define AQLO 18432
#define ASKV 36864                     /* K/V stages start */
#define AST  36864                     /* per-stage bytes: Khi,Klo,Vhi,Vlo x 9216 */
#define ALP  (ASKV + 2*AST)            /* 110592: 256 f32 row-sum partials */
#define AMSK (ALP + 1024)              /* 111616: 2 stages x 64 ints */
#define AT_SMEM (AMSK + 512)           /* 112128 */

__global__ __launch_bounds__(256, 1) void attn_mma(
    const __nv_bfloat16* __restrict__ Qhi_g, const __nv_bfloat16* __restrict__ Qlo_g,
    const __nv_bfloat16* __restrict__ Khi_g, const __nv_bfloat16* __restrict__ Klo_g,
    const __nv_bfloat16* __restrict__ Vhi_g, const __nv_bfloat16* __restrict__ Vlo_g,
    const int* __restrict__ mask,
    float* __restrict__ attn, float* __restrict__ Ctx, float* __restrict__ Lout)
{
    extern __shared__ char ash[];
    const uint32_t s0 = smem_u32(ash);
    float* Lpart = (float*)(ash + ALP);
    int*   Msk   = (int*)(ash + AMSK);

    const int t = threadIdx.x, warp = t >> 5, lane = t & 31;
    const int qw = warp >> 1, kw = warp & 1;
    const int q0 = blockIdx.x * 128, h = blockIdx.y, b = blockIdx.z;
    const int bh = b * H_ + h;
    const size_t hb = (size_t)bh * S_ * 64;
    const __nv_bfloat16* Kh_b = Khi_g + hb;
    const __nv_bfloat16* Kl_b = Klo_g + hb;
    const __nv_bfloat16* Vh_b = Vhi_g + hb;
    const __nv_bfloat16* Vl_b = Vlo_g + hb;

    Lpart[t] = 0.f;

    // ---- issue Q load (128 rows x 2 matrices), then stage 0 ----
    {
        const int mtx = t & 1, row = t >> 1;
        const __nv_bfloat16* src = (mtx ? Qlo_g : Qhi_g) + hb + (size_t)(q0 + row) * 64;
        uint32_t dst = s0 + (mtx ? AQLO : AQHI) + row * APB;
        #pragma unroll
        for (int j = 0; j < 8; j++) CP16(dst + j * 16, (const char*)src + j * 16);
    }

    #define AT_ISSUE(c) do {                                                     \
        int st = (c) & 1, kb = (c) * 64;                                         \
        int mtx = t >> 6, row = t & 63;                                          \
        const __nv_bfloat16* sp =                                                \
            (mtx == 0 ? Kh_b : mtx == 1 ? Kl_b : mtx == 2 ? Vh_b : Vl_b)         \
            + (size_t)(kb + row) * 64;                                           \
        uint32_t dst = s0 + ASKV + st * AST + mtx * 9216 + row * APB;            \
        _Pragma("unroll")                                                        \
        for (int j = 0; j < 8; j++) CP16(dst + j * 16, (const char*)sp + j * 16);\
        if (t < 16) CP16(s0 + AMSK + st * 256 + t * 16,                          \
                         (const char*)(mask + b * S_ + kb) + t * 16);            \
    } while (0)

    AT_ISSUE(0);
    CP_COMMIT();

    const int r8 = lane & 7, tl = lane >> 3;
    const int er = lane >> 2, ec = (lane & 3) * 2;
    const uint32_t a_roff = (uint32_t)((qw * 32 + (tl & 1) * 8 + r8) * APB + (tl >> 1) * 16);
    const uint32_t b_roff = (uint32_t)((kw * 32 + r8) * APB + (tl & 1) * 16);
    const uint32_t v_roff = (uint32_t)((kw * 32 + (tl & 1) * 8 + r8) * APB);

    float oacc[2][8][4];
    #pragma unroll
    for (int mt = 0; mt < 2; mt++)
        #pragma unroll
        for (int nt = 0; nt < 8; nt++)
            #pragma unroll
            for (int j = 0; j < 4; j++) oacc[mt][nt][j] = 0.f;

    for (int c = 0; c < 32; c++) {
        if (c < 31) { AT_ISSUE(c + 1); CP_COMMIT(); CP_WAIT(1); }
        else        { CP_WAIT(0); }
        __syncthreads();

        const int st = c & 1, kb = c * 64;
        const uint32_t sKh = s0 + ASKV + st * AST;
        const uint32_t sKl = sKh + 9216;
        const uint32_t sVh = sKh + 18432;
        const uint32_t sVl = sKh + 27648;

        // ---- S = Q K^T (32q x 32k per warp), split-bf16 3-term ----
        float sc[2][4][4];
        #pragma unroll
        for (int mt = 0; mt < 2; mt++)
            #pragma unroll
            for (int nf = 0; nf < 4; nf++)
                #pragma unroll
                for (int j = 0; j < 4; j++) sc[mt][nf][j] = 0.f;

        #pragma unroll
        for (int ks = 0; ks < 4; ks++) {
            uint32_t qh_[2][4], ql_[2][4];
            #pragma unroll
            for (int mt = 0; mt < 2; mt++) {
                uint32_t off = a_roff + mt * 16 * APB + ks * 32;
                ldsm_x4(qh_[mt], s0 + AQHI + off);
                ldsm_x4(ql_[mt], s0 + AQLO + off);
            }
            #pragma unroll
            for (int nf = 0; nf < 4; nf++) {
                uint32_t boff = b_roff + nf * 8 * APB + ks * 32;
                uint32_t kh_[2], kl_[2];
                ldsm_x2(kh_, sKh + boff);
                ldsm_x2(kl_, sKl + boff);
                #pragma unroll
                for (int mt = 0; mt < 2; mt++) {
                    mma16816(sc[mt][nf], qh_[mt], kh_);
                    mma16816(sc[mt][nf], qh_[mt], kl_);
                    mma16816(sc[mt][nf], ql_[mt], kh_);
                }
            }
        }

        // ---- epilogue: mask+exp, row sums, attn store, P frags ----
        uint32_t phi[2][2][4], plo[2][2][4];
        #pragma unroll
        for (int mt = 0; mt < 2; mt++) {
            float rs0 = 0.f, rs1 = 0.f;
            #pragma unroll
            for (int nf = 0; nf < 4; nf++) {
                int col = kw * 32 + nf * 8 + ec;
                int m0 = Msk[st * 64 + col], m1 = Msk[st * 64 + col + 1];
                float p00 = m0 ? __expf(sc[mt][nf][0]) : 0.f;
                float p01 = m1 ? __expf(sc[mt][nf][1]) : 0.f;
                float p10 = m0 ? __expf(sc[mt][nf][2]) : 0.f;
                float p11 = m1 ? __expf(sc[mt][nf][3]) : 0.f;
                rs0 += p00 + p01; rs1 += p10 + p11;
                if (attn) {
                    int q = q0 + qw * 32 + mt * 16 + er;
                    size_t ro = ((size_t)bh * S_ + q) * S_ + kb + col;
                    *(float2*)&attn[ro]          = make_float2(p00, p01);
                    *(float2*)&attn[ro + 8 * S_] = make_float2(p10, p11);
                }
                int kf = nf >> 1, hf = (nf & 1) * 2;
                phi[mt][kf][hf]     = packbf(bf_round(p00), bf_round(p01));
                phi[mt][kf][hf + 1] = packbf(bf_round(p10), bf_round(p11));
                plo[mt][kf][hf]     = packbf(p00 - bf_round(p00), p01 - bf_round(p01));
                plo[mt][kf][hf + 1] = packbf(p10 - bf_round(p10), p11 - bf_round(p11));
            }
            rs0 += __shfl_xor_sync(0xffffffffu, rs0, 1);
            rs0 += __shfl_xor_sync(0xffffffffu, rs0, 2);
            rs1 += __shfl_xor_sync(0xffffffffu, rs1, 1);
            rs1 += __shfl_xor_sync(0xffffffffu, rs1, 2);
            if ((lane & 3) == 0) {
                int q = qw * 32 + mt * 16 + er;
                Lpart[kw * 128 + q]     += rs0;
                Lpart[kw * 128 + q + 8] += rs1;
            }
        }

        // ---- O += P V (keys slice of this warp), split 3-term ----
        #pragma unroll
        for (int kf = 0; kf < 2; kf++) {
            #pragma unroll
            for (int nf2 = 0; nf2 < 8; nf2++) {
                uint32_t voff = v_roff + kf * 16 * APB + nf2 * 16;
                uint32_t vh_[2], vl_[2];
                ldsm_x2t(vh_, sVh + voff);
                ldsm_x2t(vl_, sVl + voff);
                #pragma unroll
                for (int mt = 0; mt < 2; mt++) {
                    mma16816(oacc[mt][nf2], phi[mt][kf], vh_);
                    mma16816(oacc[mt][nf2], phi[mt][kf], vl_);
                    mma16816(oacc[mt][nf2], plo[mt][kf], vh_);
                }
            }
        }
        __syncthreads();
    }

    // ---- reduce O across the 2 k-warps via smem, normalize, write ----
    float* Ored = (float*)(ash + ASKV);        // 128 x 68 f32 = 34816B, fits
    if (kw == 1) {
        #pragma unroll
        for (int mt = 0; mt < 2; mt++)
            #pragma unroll
            for (int nf2 = 0; nf2 < 8; nf2++) {
                int q = qw * 32 + mt * 16 + er, d = nf2 * 8 + ec;
                *(float2*)&Ored[q * 68 + d]       = make_float2(oacc[mt][nf2][0], oacc[mt][nf2][1]);
                *(float2*)&Ored[(q + 8) * 68 + d] = make_float2(oacc[mt][nf2][2], oacc[mt][nf2][3]);
            }
    }
    __syncthreads();
    if (kw == 0) {
        #pragma unroll
        for (int mt = 0; mt < 2; mt++) {
            int qA = qw * 32 + mt * 16 + er;
            float invA = 1.f / (Lpart[qA] + Lpart[128 + qA]);
            float invB = 1.f / (Lpart[qA + 8] + Lpart[128 + qA + 8]);
            #pragma unroll
            for (int nf2 = 0; nf2 < 8; nf2++) {
                int d = nf2 * 8 + ec;
                float2 oA = *(float2*)&Ored[qA * 68 + d];
                float2 oB = *(float2*)&Ored[(qA + 8) * 68 + d];
                oA.x = (oA.x + oacc[mt][nf2][0]) * invA;
                oA.y = (oA.y + oacc[mt][nf2][1]) * invA;
                oB.x = (oB.x + oacc[mt][nf2][2]) * invB;
                oB.y = (oB.y + oacc[mt][nf2][3]) * invB;
                size_t oo = ((size_t)b * S_ + q0 + qA) * D_ + h * 64 + d;
                *(float2*)&Ctx[oo]          = oA;
                *(float2*)&Ctx[oo + 8 * D_] = oB;
            }
        }
    }
    if (t < 128) Lout[(size_t)bh * S_ + q0 + t] = Lpart[t] + Lpart[128 + t];
}

// ===========================================================================
// Normalize attn rows by 1/rowsum
// ===========================================================================
__global__ __launch_bounds__(256) void rescale_kernel(
    float* __restrict__ attn, const float* __restrict__ L)
{
    const int row = blockIdx.x;
    const float inv = 1.0f / L[row];
    float4* p = (float4*)(attn + (size_t)row * 2048);
    const int t = threadIdx.x;
    #pragma unroll
    for (int c = t; c < 512; c += 256) {
        float4 v = p[c];
        v.x *= inv; v.y *= inv; v.z *= inv; v.w *= inv;
        p[c] = v;
    }
}

// ===========================================================================
extern "C" void kernel_launch(void* const* d_in, const int* in_sizes, int n_in,
                              void* d_out, int out_size)
{
    const float* query = (const float*)d_in[0];
    const float* key   = (const float*)d_in[1];
    const float* value = (const float*)d_in[2];
    const int*   mask  = (const int*)d_in[3];
    const float* W_Q   = (const float*)d_in[4];
    const float* W_K   = (const float*)d_in[5];
    const float* W_V   = (const float*)d_in[6];
    const float* W_O   = (const float*)d_in[7];

    float* out = (float*)d_out;
    bool hasAttn = (out_size >= OUT_ELEMS + ATT_ELEMS);
    float* attn = hasAttn ? (out + OUT_ELEMS) : nullptr;

    __nv_bfloat16 *qh, *ql, *kh, *kl, *vh, *vl;
    float *gc, *gl;
    cudaGetSymbolAddress((void**)&qh, g_Qhi);
    cudaGetSymbolAddress((void**)&ql, g_Qlo);
    cudaGetSymbolAddress((void**)&kh, g_Khi);
    cudaGetSymbolAddress((void**)&kl, g_Klo);
    cudaGetSymbolAddress((void**)&vh, g_Vhi);
    cudaGetSymbolAddress((void**)&vl, g_Vlo);
    cudaGetSymbolAddress((void**)&gc, g_C);
    cudaGetSymbolAddress((void**)&gl, g_L);

    cudaFuncSetAttribute((const void*)attn_mma,
                         cudaFuncAttributeMaxDynamicSharedMemorySize, AT_SMEM);
    cudaFuncSetAttribute((const void*)mma_gemm,
                         cudaFuncAttributeMaxDynamicSharedMemorySize, GT_SMEM);

    dim3 gg(8, 32);   // N/128 x M/128
    mma_gemm<<<gg, 256, GT_SMEM>>>(query, W_Q, qh, ql, nullptr, 0.125f, 0);
    mma_gemm<<<gg, 256, GT_SMEM>>>(key,   W_K, kh, kl, nullptr, 1.0f,   0);
    mma_gemm<<<gg, 256, GT_SMEM>>>(value, W_V, vh, vl, nullptr, 1.0f,   0);
    attn_mma<<<dim3(16, 16, 2), 256, AT_SMEM>>>(qh, ql, kh, kl, vh, vl, mask, attn, gc, gl);
    if (hasAttn) rescale_kernel<<<B_*H_*S_, 256>>>(attn, gl);
    mma_gemm<<<gg, 256, GT_SMEM>>>(gc, W_O, nullptr, nullptr, out, 1.0f, 1);
}